// round 1
// baseline (speedup 1.0000x reference)
#include <cuda_runtime.h>
#include <cuda_bf16.h>

// Problem constants
#define BATCH 2048
#define TT    609
#define NIN   5
#define HH    8
#define D_LSTM (TT * HH)     // 4872
#define N1    4096
#define N2    1024
#define N3    609            // == TT

// Scratch (no cudaMalloc allowed) ---------------------------------------------
__device__ float g_lstm_out[BATCH * D_LSTM];   // [2048, 4872]
__device__ float g_act1[BATCH * N1];           // [2048, 4096]
__device__ float g_act2[BATCH * N2];           // [2048, 1024]

// ---------------------------------------------------------------------------
// Fused 3-layer LSTM. 16 threads per batch element (2 elements per warp).
// Within a 16-lane group: sub = lane&15, j = sub&7, half = sub>>3.
//   half==0 thread: gate rows j (i-gate) and 16+j (g-gate)
//   half==1 thread: gate rows 8+j (f-gate) and 24+j (o-gate)
// Cell state c_j lives in half==0 lanes; h broadcast via shfl width=16.
// ---------------------------------------------------------------------------

__device__ __forceinline__ float sigmoidf_fast(float v) {
    float e = __expf(-v);
    return __fdividef(1.0f, 1.0f + e);
}

template <int NI>
__device__ __forceinline__ float cell_step(
    const float (&wA)[NI], const float (&wB)[NI],
    const float (&uA)[HH], const float (&uB)[HH],
    float bA, float bB,
    const float (&in)[NI], float (&h)[HH], float& c, int half)
{
    float gA = bA, gB = bB;
#pragma unroll
    for (int i = 0; i < NI; i++) {
        gA = fmaf(wA[i], in[i], gA);
        gB = fmaf(wB[i], in[i], gB);
    }
#pragma unroll
    for (int k = 0; k < HH; k++) {
        gA = fmaf(uA[k], h[k], gA);
        gB = fmaf(uB[k], h[k], gB);
    }
    // gA is i (half0) or f (half1): sigmoid
    float va = sigmoidf_fast(gA);
    // gB is g (half0 -> tanh) or o (half1 -> sigmoid). Branchless via selects.
    float e  = __expf(half ? -gB : (-2.0f * gB));
    float r  = __fdividef(1.0f, 1.0f + e);
    float vb = half ? r : fmaf(2.0f, r, -1.0f);

    // exchange across halves: half0 receives (f, o), half1 receives (i, g)
    float pa = __shfl_xor_sync(0xffffffffu, va, 8);
    float pb = __shfl_xor_sync(0xffffffffu, vb, 8);

    // half0: i=va, g=vb, f=pa, o=pb
    c = fmaf(pa, c, va * vb);                                  // c = f*c + i*g
    float th = fmaf(2.0f, __fdividef(1.0f, 1.0f + __expf(-2.0f * c)), -1.0f);
    float hv = pb * th;                                        // h = o * tanh(c)

    // broadcast h_0..h_7 (valid in lanes 0-7 of each 16-group) to all 16 lanes
#pragma unroll
    for (int k = 0; k < HH; k++)
        h[k] = __shfl_sync(0xffffffffu, hv, k, 16);
    return hv;
}

__global__ __launch_bounds__(256, 1)
void lstm3_kernel(
    const float* __restrict__ x,
    const float* __restrict__ Wih1, const float* __restrict__ Whh1,
    const float* __restrict__ bih1, const float* __restrict__ bhh1,
    const float* __restrict__ Wih2, const float* __restrict__ Whh2,
    const float* __restrict__ bih2, const float* __restrict__ bhh2,
    const float* __restrict__ Wih3, const float* __restrict__ Whh3,
    const float* __restrict__ bih3, const float* __restrict__ bhh3,
    float* __restrict__ out)
{
    const int tid  = threadIdx.x;
    const int grp  = tid >> 4;       // group within block (0..15)
    const int sub  = tid & 15;
    const int b    = blockIdx.x * 16 + grp;
    const int j    = sub & 7;
    const int half = sub >> 3;

    const int rowA = half * 8 + j;        // i (half0) / f (half1)
    const int rowB = 16 + half * 8 + j;   // g (half0) / o (half1)

    // ---- load weights to registers ----
    float wi1A[NIN], wi1B[NIN], uh1A[HH], uh1B[HH];
#pragma unroll
    for (int i = 0; i < NIN; i++) { wi1A[i] = Wih1[rowA * NIN + i]; wi1B[i] = Wih1[rowB * NIN + i]; }
#pragma unroll
    for (int k = 0; k < HH;  k++) { uh1A[k] = Whh1[rowA * HH + k]; uh1B[k] = Whh1[rowB * HH + k]; }
    float b1A = bih1[rowA] + bhh1[rowA];
    float b1B = bih1[rowB] + bhh1[rowB];

    float wi2A[HH], wi2B[HH], uh2A[HH], uh2B[HH];
#pragma unroll
    for (int k = 0; k < HH; k++) {
        wi2A[k] = Wih2[rowA * HH + k]; wi2B[k] = Wih2[rowB * HH + k];
        uh2A[k] = Whh2[rowA * HH + k]; uh2B[k] = Whh2[rowB * HH + k];
    }
    float b2A = bih2[rowA] + bhh2[rowA];
    float b2B = bih2[rowB] + bhh2[rowB];

    float wi3A[HH], wi3B[HH], uh3A[HH], uh3B[HH];
#pragma unroll
    for (int k = 0; k < HH; k++) {
        wi3A[k] = Wih3[rowA * HH + k]; wi3B[k] = Wih3[rowB * HH + k];
        uh3A[k] = Whh3[rowA * HH + k]; uh3B[k] = Whh3[rowB * HH + k];
    }
    float b3A = bih3[rowA] + bhh3[rowA];
    float b3B = bih3[rowB] + bhh3[rowB];

    // ---- state ----
    float h1[HH], h2[HH], h3[HH];
#pragma unroll
    for (int k = 0; k < HH; k++) { h1[k] = 0.f; h2[k] = 0.f; h3[k] = 0.f; }
    float c1 = 0.f, c2 = 0.f, c3 = 0.f;

    const float* xrow = x + (size_t)b * TT * NIN;
    float* outp = out + (size_t)b * D_LSTM;

    // prefetch t=0 input (all 16 lanes same address -> L1 broadcast)
    float xn[NIN];
#pragma unroll
    for (int i = 0; i < NIN; i++) xn[i] = xrow[i];

    for (int t = 0; t < TT; t++) {
        float xc[NIN];
#pragma unroll
        for (int i = 0; i < NIN; i++) xc[i] = xn[i];
        const int tn = (t + 1 < TT) ? (t + 1) : (TT - 1);
#pragma unroll
        for (int i = 0; i < NIN; i++) xn[i] = xrow[tn * NIN + i];

        (void)cell_step<NIN>(wi1A, wi1B, uh1A, uh1B, b1A, b1B, xc, h1, c1, half);
        (void)cell_step<HH >(wi2A, wi2B, uh2A, uh2B, b2A, b2B, h1, h2, c2, half);
        float hv3 = cell_step<HH>(wi3A, wi3B, uh3A, uh3B, b3A, b3B, h2, h3, c3, half);

        if (half == 0)
            outp[t * HH + j] = hv3;   // feature layout: flatten([B,T,H]) -> t*8+j
    }
}

// ---------------------------------------------------------------------------
// Tiled fp32 GEMM:  C[M,N] = A[M,K] @ W[N,K]^T + bias, optional relu.
// A, W row-major (K contiguous). M multiple of BM, K multiple of BK; N guarded.
// ---------------------------------------------------------------------------
template <int BM, int BN, int BK, int TM, int TN, bool RELU>
__global__ __launch_bounds__((BM / TM) * (BN / TN))
void gemm_bias_kernel(const float* __restrict__ A, const float* __restrict__ W,
                      const float* __restrict__ bias, float* __restrict__ C,
                      int M, int N, int K)
{
    constexpr int THREADS = (BM / TM) * (BN / TN);
    __shared__ __align__(16) float As[BK][BM];
    __shared__ __align__(16) float Bs[BK][BN];

    const int tid = threadIdx.x;
    const int tx  = tid % (BN / TN);
    const int ty  = tid / (BN / TN);
    const int m0  = blockIdx.y * BM;
    const int n0  = blockIdx.x * BN;

    float acc[TM][TN];
#pragma unroll
    for (int i = 0; i < TM; i++)
#pragma unroll
        for (int jj = 0; jj < TN; jj++) acc[i][jj] = 0.f;

    constexpr int AV = BM * BK / 4;
    constexpr int BV = BN * BK / 4;

    for (int k0 = 0; k0 < K; k0 += BK) {
#pragma unroll
        for (int idx = tid; idx < AV; idx += THREADS) {
            const int row = idx / (BK / 4);
            const int kq  = idx % (BK / 4);
            const float4 v = *reinterpret_cast<const float4*>(
                &A[(size_t)(m0 + row) * K + k0 + kq * 4]);
            As[kq * 4 + 0][row] = v.x;
            As[kq * 4 + 1][row] = v.y;
            As[kq * 4 + 2][row] = v.z;
            As[kq * 4 + 3][row] = v.w;
        }
#pragma unroll
        for (int idx = tid; idx < BV; idx += THREADS) {
            const int row = idx / (BK / 4);
            const int kq  = idx % (BK / 4);
            float4 v = make_float4(0.f, 0.f, 0.f, 0.f);
            if (n0 + row < N)
                v = *reinterpret_cast<const float4*>(
                    &W[(size_t)(n0 + row) * K + k0 + kq * 4]);
            Bs[kq * 4 + 0][row] = v.x;
            Bs[kq * 4 + 1][row] = v.y;
            Bs[kq * 4 + 2][row] = v.z;
            Bs[kq * 4 + 3][row] = v.w;
        }
        __syncthreads();

#pragma unroll
        for (int kk = 0; kk < BK; kk++) {
            float ar[TM], br[TN];
#pragma unroll
            for (int q = 0; q < TM / 4; q++) {
                const float4 v = *reinterpret_cast<const float4*>(&As[kk][ty * TM + 4 * q]);
                ar[4 * q + 0] = v.x; ar[4 * q + 1] = v.y;
                ar[4 * q + 2] = v.z; ar[4 * q + 3] = v.w;
            }
#pragma unroll
            for (int q = 0; q < TN / 4; q++) {
                const float4 v = *reinterpret_cast<const float4*>(&Bs[kk][tx * TN + 4 * q]);
                br[4 * q + 0] = v.x; br[4 * q + 1] = v.y;
                br[4 * q + 2] = v.z; br[4 * q + 3] = v.w;
            }
#pragma unroll
            for (int i = 0; i < TM; i++)
#pragma unroll
                for (int jj = 0; jj < TN; jj++)
                    acc[i][jj] = fmaf(ar[i], br[jj], acc[i][jj]);
        }
        __syncthreads();
    }

    // epilogue: bias (+relu), guarded stores
#pragma unroll
    for (int i = 0; i < TM; i++) {
        const int m = m0 + ty * TM + i;
#pragma unroll
        for (int jj = 0; jj < TN; jj++) {
            const int n = n0 + tx * TN + jj;
            if (n < N) {
                float v = acc[i][jj] + bias[n];
                if (RELU) v = fmaxf(v, 0.f);
                C[(size_t)m * N + n] = v;
            }
        }
    }
}

// ---------------------------------------------------------------------------
extern "C" void kernel_launch(void* const* d_in, const int* in_sizes, int n_in,
                              void* d_out, int out_size)
{
    const float* x    = (const float*)d_in[0];
    const float* Wih1 = (const float*)d_in[1];
    const float* Whh1 = (const float*)d_in[2];
    const float* bih1 = (const float*)d_in[3];
    const float* bhh1 = (const float*)d_in[4];
    const float* Wih2 = (const float*)d_in[5];
    const float* Whh2 = (const float*)d_in[6];
    const float* bih2 = (const float*)d_in[7];
    const float* bhh2 = (const float*)d_in[8];
    const float* Wih3 = (const float*)d_in[9];
    const float* Whh3 = (const float*)d_in[10];
    const float* bih3 = (const float*)d_in[11];
    const float* bhh3 = (const float*)d_in[12];
    const float* W1   = (const float*)d_in[13];
    const float* b1   = (const float*)d_in[14];
    const float* W2   = (const float*)d_in[15];
    const float* b2   = (const float*)d_in[16];
    const float* W3   = (const float*)d_in[17];
    const float* b3   = (const float*)d_in[18];
    float* out = (float*)d_out;

    float *lstm_o, *a1, *a2;
    cudaGetSymbolAddress((void**)&lstm_o, g_lstm_out);
    cudaGetSymbolAddress((void**)&a1, g_act1);
    cudaGetSymbolAddress((void**)&a2, g_act2);

    // 1) fused 3-layer LSTM: 2048 elems * 16 threads = 128 blocks x 256
    lstm3_kernel<<<BATCH / 16, 256>>>(x,
        Wih1, Whh1, bih1, bhh1,
        Wih2, Whh2, bih2, bhh2,
        Wih3, Whh3, bih3, bhh3,
        lstm_o);

    // 2) MLP head
    {   // [2048,4872] x [4096,4872]^T -> relu -> [2048,4096]
        dim3 grid(N1 / 128, BATCH / 128);
        gemm_bias_kernel<128, 128, 8, 8, 8, true><<<grid, 256>>>(
            lstm_o, W1, b1, a1, BATCH, N1, D_LSTM);
    }
    {   // [2048,4096] x [1024,4096]^T -> relu -> [2048,1024]
        dim3 grid(N2 / 64, BATCH / 128);
        gemm_bias_kernel<128, 64, 8, 8, 4, true><<<grid, 256>>>(
            a1, W2, b2, a2, BATCH, N2, N1);
    }
    {   // [2048,1024] x [609,1024]^T -> [2048,609]
        dim3 grid((N3 + 63) / 64, BATCH / 128);
        gemm_bias_kernel<128, 64, 8, 8, 4, false><<<grid, 256>>>(
            a2, W3, b3, out, BATCH, N3, N2);
    }
}

// round 2
// speedup vs baseline: 2.1483x; 2.1483x over previous
#include <cuda_runtime.h>
#include <cuda_bf16.h>
#include <cstdint>

// Problem constants
#define BATCH 2048
#define TT    609
#define NIN   5
#define HH    8
#define D_LSTM (TT * HH)     // 4872
#define N1    4096
#define N2    1024
#define N3    609            // == TT

// Scratch (no cudaMalloc allowed) ---------------------------------------------
__device__ float g_lstm_out[BATCH * D_LSTM];   // [2048, 4872]
__device__ float g_act1[BATCH * N1];           // [2048, 4096]
__device__ float g_act2[BATCH * N2];           // [2048, 1024]

// ---------------------------------------------------------------------------
// Fused 3-layer LSTM (unchanged from R1). 16 threads per batch element.
// ---------------------------------------------------------------------------

__device__ __forceinline__ float sigmoidf_fast(float v) {
    float e = __expf(-v);
    return __fdividef(1.0f, 1.0f + e);
}

template <int NI>
__device__ __forceinline__ float cell_step(
    const float (&wA)[NI], const float (&wB)[NI],
    const float (&uA)[HH], const float (&uB)[HH],
    float bA, float bB,
    const float (&in)[NI], float (&h)[HH], float& c, int half)
{
    float gA = bA, gB = bB;
#pragma unroll
    for (int i = 0; i < NI; i++) {
        gA = fmaf(wA[i], in[i], gA);
        gB = fmaf(wB[i], in[i], gB);
    }
#pragma unroll
    for (int k = 0; k < HH; k++) {
        gA = fmaf(uA[k], h[k], gA);
        gB = fmaf(uB[k], h[k], gB);
    }
    float va = sigmoidf_fast(gA);
    float e  = __expf(half ? -gB : (-2.0f * gB));
    float r  = __fdividef(1.0f, 1.0f + e);
    float vb = half ? r : fmaf(2.0f, r, -1.0f);

    float pa = __shfl_xor_sync(0xffffffffu, va, 8);
    float pb = __shfl_xor_sync(0xffffffffu, vb, 8);

    c = fmaf(pa, c, va * vb);
    float th = fmaf(2.0f, __fdividef(1.0f, 1.0f + __expf(-2.0f * c)), -1.0f);
    float hv = pb * th;

#pragma unroll
    for (int k = 0; k < HH; k++)
        h[k] = __shfl_sync(0xffffffffu, hv, k, 16);
    return hv;
}

__global__ __launch_bounds__(256, 1)
void lstm3_kernel(
    const float* __restrict__ x,
    const float* __restrict__ Wih1, const float* __restrict__ Whh1,
    const float* __restrict__ bih1, const float* __restrict__ bhh1,
    const float* __restrict__ Wih2, const float* __restrict__ Whh2,
    const float* __restrict__ bih2, const float* __restrict__ bhh2,
    const float* __restrict__ Wih3, const float* __restrict__ Whh3,
    const float* __restrict__ bih3, const float* __restrict__ bhh3,
    float* __restrict__ out)
{
    const int tid  = threadIdx.x;
    const int grp  = tid >> 4;
    const int sub  = tid & 15;
    const int b    = blockIdx.x * 16 + grp;
    const int j    = sub & 7;
    const int half = sub >> 3;

    const int rowA = half * 8 + j;
    const int rowB = 16 + half * 8 + j;

    float wi1A[NIN], wi1B[NIN], uh1A[HH], uh1B[HH];
#pragma unroll
    for (int i = 0; i < NIN; i++) { wi1A[i] = Wih1[rowA * NIN + i]; wi1B[i] = Wih1[rowB * NIN + i]; }
#pragma unroll
    for (int k = 0; k < HH;  k++) { uh1A[k] = Whh1[rowA * HH + k]; uh1B[k] = Whh1[rowB * HH + k]; }
    float b1A = bih1[rowA] + bhh1[rowA];
    float b1B = bih1[rowB] + bhh1[rowB];

    float wi2A[HH], wi2B[HH], uh2A[HH], uh2B[HH];
#pragma unroll
    for (int k = 0; k < HH; k++) {
        wi2A[k] = Wih2[rowA * HH + k]; wi2B[k] = Wih2[rowB * HH + k];
        uh2A[k] = Whh2[rowA * HH + k]; uh2B[k] = Whh2[rowB * HH + k];
    }
    float b2A = bih2[rowA] + bhh2[rowA];
    float b2B = bih2[rowB] + bhh2[rowB];

    float wi3A[HH], wi3B[HH], uh3A[HH], uh3B[HH];
#pragma unroll
    for (int k = 0; k < HH; k++) {
        wi3A[k] = Wih3[rowA * HH + k]; wi3B[k] = Wih3[rowB * HH + k];
        uh3A[k] = Whh3[rowA * HH + k]; uh3B[k] = Whh3[rowB * HH + k];
    }
    float b3A = bih3[rowA] + bhh3[rowA];
    float b3B = bih3[rowB] + bhh3[rowB];

    float h1[HH], h2[HH], h3[HH];
#pragma unroll
    for (int k = 0; k < HH; k++) { h1[k] = 0.f; h2[k] = 0.f; h3[k] = 0.f; }
    float c1 = 0.f, c2 = 0.f, c3 = 0.f;

    const float* xrow = x + (size_t)b * TT * NIN;
    float* outp = out + (size_t)b * D_LSTM;

    float xn[NIN];
#pragma unroll
    for (int i = 0; i < NIN; i++) xn[i] = xrow[i];

    for (int t = 0; t < TT; t++) {
        float xc[NIN];
#pragma unroll
        for (int i = 0; i < NIN; i++) xc[i] = xn[i];
        const int tn = (t + 1 < TT) ? (t + 1) : (TT - 1);
#pragma unroll
        for (int i = 0; i < NIN; i++) xn[i] = xrow[tn * NIN + i];

        (void)cell_step<NIN>(wi1A, wi1B, uh1A, uh1B, b1A, b1B, xc, h1, c1, half);
        (void)cell_step<HH >(wi2A, wi2B, uh2A, uh2B, b2A, b2B, h1, h2, c2, half);
        float hv3 = cell_step<HH>(wi3A, wi3B, uh3A, uh3B, b3A, b3B, h2, h3, c3, half);

        if (half == 0)
            outp[t * HH + j] = hv3;
    }
}

// ---------------------------------------------------------------------------
// tf32 tensor-core GEMM:  C[M,N] = A[M,K] @ W[N,K]^T + bias, optional relu.
// A row-major (mma "row"), W row-major over [N,K] == B col-major (mma "col").
// mma.sync.aligned.m16n8k8.f32.tf32.tf32.f32, fp32 accumulate.
// ---------------------------------------------------------------------------

__device__ __forceinline__ uint32_t f2tf32(float f) {
    uint32_t r;
    asm("cvt.rna.tf32.f32 %0, %1;" : "=r"(r) : "f"(f));
    return r;
}

__device__ __forceinline__ void mma_tf32(float (&c)[4], const uint32_t (&a)[4],
                                         const uint32_t (&b)[2]) {
    asm volatile(
        "mma.sync.aligned.m16n8k8.row.col.f32.tf32.tf32.f32 "
        "{%0,%1,%2,%3}, {%4,%5,%6,%7}, {%8,%9}, {%0,%1,%2,%3};"
        : "+f"(c[0]), "+f"(c[1]), "+f"(c[2]), "+f"(c[3])
        : "r"(a[0]), "r"(a[1]), "r"(a[2]), "r"(a[3]), "r"(b[0]), "r"(b[1]));
}

template <int BM, int BN, int BK, int WARPS_M, int WARPS_N, bool RELU>
__global__ __launch_bounds__(WARPS_M * WARPS_N * 32)
void gemm_tf32_kernel(const float* __restrict__ A, const float* __restrict__ W,
                      const float* __restrict__ bias, float* __restrict__ C,
                      int M, int N, int K)
{
    constexpr int THREADS = WARPS_M * WARPS_N * 32;
    constexpr int WM = BM / WARPS_M;       // warp tile M
    constexpr int WN = BN / WARPS_N;       // warp tile N
    constexpr int MT = WM / 16;            // mma tiles per warp (M)
    constexpr int NT = WN / 8;             // mma tiles per warp (N)
    constexpr int LD = BK + 4;             // smem row stride (words)

    __shared__ __align__(16) uint32_t As[BM * LD];
    __shared__ __align__(16) uint32_t Bs[BN * LD];

    const int tid  = threadIdx.x;
    const int lane = tid & 31;
    const int warp = tid >> 5;
    const int wm   = warp / WARPS_N;
    const int wn   = warp % WARPS_N;
    const int g    = lane >> 2;            // 0..7
    const int t    = lane & 3;             // 0..3

    const int m0 = blockIdx.y * BM;
    const int n0 = blockIdx.x * BN;

    float acc[MT][NT][4];
#pragma unroll
    for (int i = 0; i < MT; i++)
#pragma unroll
        for (int j = 0; j < NT; j++)
#pragma unroll
            for (int q = 0; q < 4; q++) acc[i][j][q] = 0.f;

    constexpr int AVEC = BM * (BK / 4);    // float4 loads for A tile
    constexpr int BVEC = BN * (BK / 4);

    for (int k0 = 0; k0 < K; k0 += BK) {
        // ---- A tile -> smem (tf32) ----
#pragma unroll
        for (int idx = tid; idx < AVEC; idx += THREADS) {
            const int row = idx / (BK / 4);
            const int kq  = idx % (BK / 4);
            const int kg  = k0 + kq * 4;
            float4 v = make_float4(0.f, 0.f, 0.f, 0.f);
            if (kg < K)
                v = *reinterpret_cast<const float4*>(&A[(size_t)(m0 + row) * K + kg]);
            uint4 u;
            u.x = f2tf32(v.x); u.y = f2tf32(v.y);
            u.z = f2tf32(v.z); u.w = f2tf32(v.w);
            *reinterpret_cast<uint4*>(&As[row * LD + kq * 4]) = u;
        }
        // ---- B tile (W rows) -> smem (tf32), N guarded ----
#pragma unroll
        for (int idx = tid; idx < BVEC; idx += THREADS) {
            const int row = idx / (BK / 4);
            const int kq  = idx % (BK / 4);
            const int kg  = k0 + kq * 4;
            float4 v = make_float4(0.f, 0.f, 0.f, 0.f);
            if ((n0 + row) < N && kg < K)
                v = *reinterpret_cast<const float4*>(&W[(size_t)(n0 + row) * K + kg]);
            uint4 u;
            u.x = f2tf32(v.x); u.y = f2tf32(v.y);
            u.z = f2tf32(v.z); u.w = f2tf32(v.w);
            *reinterpret_cast<uint4*>(&Bs[row * LD + kq * 4]) = u;
        }
        __syncthreads();

#pragma unroll
        for (int kk = 0; kk < BK; kk += 8) {
            uint32_t af[MT][4], bf[NT][2];
#pragma unroll
            for (int mt = 0; mt < MT; mt++) {
                const int r = wm * WM + mt * 16 + g;
                af[mt][0] = As[(r    ) * LD + kk + t    ];
                af[mt][1] = As[(r + 8) * LD + kk + t    ];
                af[mt][2] = As[(r    ) * LD + kk + t + 4];
                af[mt][3] = As[(r + 8) * LD + kk + t + 4];
            }
#pragma unroll
            for (int nt = 0; nt < NT; nt++) {
                const int cc = wn * WN + nt * 8 + g;
                bf[nt][0] = Bs[cc * LD + kk + t    ];
                bf[nt][1] = Bs[cc * LD + kk + t + 4];
            }
#pragma unroll
            for (int mt = 0; mt < MT; mt++)
#pragma unroll
                for (int nt = 0; nt < NT; nt++)
                    mma_tf32(acc[mt][nt], af[mt], bf[nt]);
        }
        __syncthreads();
    }

    // ---- epilogue: bias (+relu), guarded stores ----
#pragma unroll
    for (int mt = 0; mt < MT; mt++) {
        const int r0 = m0 + wm * WM + mt * 16 + g;
        const int r1 = r0 + 8;
#pragma unroll
        for (int nt = 0; nt < NT; nt++) {
            const int cbase = n0 + wn * WN + nt * 8 + 2 * t;
#pragma unroll
            for (int q = 0; q < 2; q++) {
                const int cn = cbase + q;
                if (cn < N) {
                    const float bv = bias[cn];
                    float v0 = acc[mt][nt][q] + bv;
                    float v1 = acc[mt][nt][2 + q] + bv;
                    if (RELU) { v0 = fmaxf(v0, 0.f); v1 = fmaxf(v1, 0.f); }
                    C[(size_t)r0 * N + cn] = v0;
                    C[(size_t)r1 * N + cn] = v1;
                }
            }
        }
    }
}

// ---------------------------------------------------------------------------
extern "C" void kernel_launch(void* const* d_in, const int* in_sizes, int n_in,
                              void* d_out, int out_size)
{
    const float* x    = (const float*)d_in[0];
    const float* Wih1 = (const float*)d_in[1];
    const float* Whh1 = (const float*)d_in[2];
    const float* bih1 = (const float*)d_in[3];
    const float* bhh1 = (const float*)d_in[4];
    const float* Wih2 = (const float*)d_in[5];
    const float* Whh2 = (const float*)d_in[6];
    const float* bih2 = (const float*)d_in[7];
    const float* bhh2 = (const float*)d_in[8];
    const float* Wih3 = (const float*)d_in[9];
    const float* Whh3 = (const float*)d_in[10];
    const float* bih3 = (const float*)d_in[11];
    const float* bhh3 = (const float*)d_in[12];
    const float* W1   = (const float*)d_in[13];
    const float* b1   = (const float*)d_in[14];
    const float* W2   = (const float*)d_in[15];
    const float* b2   = (const float*)d_in[16];
    const float* W3   = (const float*)d_in[17];
    const float* b3   = (const float*)d_in[18];
    float* out = (float*)d_out;

    float *lstm_o, *a1, *a2;
    cudaGetSymbolAddress((void**)&lstm_o, g_lstm_out);
    cudaGetSymbolAddress((void**)&a1, g_act1);
    cudaGetSymbolAddress((void**)&a2, g_act2);

    // 1) fused 3-layer LSTM
    lstm3_kernel<<<BATCH / 16, 256>>>(x,
        Wih1, Whh1, bih1, bhh1,
        Wih2, Whh2, bih2, bhh2,
        Wih3, Whh3, bih3, bhh3,
        lstm_o);

    // 2) MLP head (tf32 tensor cores)
    {   // [2048,4872] x [4096,4872]^T -> relu -> [2048,4096]
        dim3 grid(N1 / 128, BATCH / 128);
        gemm_tf32_kernel<128, 128, 32, 2, 4, true><<<grid, 256>>>(
            lstm_o, W1, b1, a1, BATCH, N1, D_LSTM);
    }
    {   // [2048,4096] x [1024,4096]^T -> relu -> [2048,1024]
        dim3 grid(N2 / 64, BATCH / 128);
        gemm_tf32_kernel<128, 64, 32, 2, 4, true><<<grid, 256>>>(
            a1, W2, b2, a2, BATCH, N2, N1);
    }
    {   // [2048,1024] x [609,1024]^T -> [2048,609]
        dim3 grid((N3 + 63) / 64, BATCH / 128);
        gemm_tf32_kernel<128, 64, 32, 2, 4, false><<<grid, 256>>>(
            a2, W3, b3, out, BATCH, N3, N2);
    }
}

// round 4
// speedup vs baseline: 2.5871x; 1.2043x over previous
#include <cuda_runtime.h>
#include <cuda_bf16.h>
#include <cstdint>

// Problem constants
#define BATCH 2048
#define TT    609
#define NIN   5
#define HH    8
#define D_LSTM (TT * HH)     // 4872
#define N1    4096
#define N2    1024
#define N3    609            // == TT

// Scratch (no cudaMalloc allowed) ---------------------------------------------
__device__ float g_lstm_out[BATCH * D_LSTM];   // [2048, 4872]
__device__ float g_act1[BATCH * N1];           // [2048, 4096]
__device__ float g_act2[BATCH * N2];           // [2048, 1024]

// ---------------------------------------------------------------------------
// Fused 3-layer LSTM (unchanged). 16 threads per batch element.
// ---------------------------------------------------------------------------

__device__ __forceinline__ float sigmoidf_fast(float v) {
    float e = __expf(-v);
    return __fdividef(1.0f, 1.0f + e);
}

template <int NI>
__device__ __forceinline__ float cell_step(
    const float (&wA)[NI], const float (&wB)[NI],
    const float (&uA)[HH], const float (&uB)[HH],
    float bA, float bB,
    const float (&in)[NI], float (&h)[HH], float& c, int half)
{
    float gA = bA, gB = bB;
#pragma unroll
    for (int i = 0; i < NI; i++) {
        gA = fmaf(wA[i], in[i], gA);
        gB = fmaf(wB[i], in[i], gB);
    }
#pragma unroll
    for (int k = 0; k < HH; k++) {
        gA = fmaf(uA[k], h[k], gA);
        gB = fmaf(uB[k], h[k], gB);
    }
    float va = sigmoidf_fast(gA);
    float e  = __expf(half ? -gB : (-2.0f * gB));
    float r  = __fdividef(1.0f, 1.0f + e);
    float vb = half ? r : fmaf(2.0f, r, -1.0f);

    float pa = __shfl_xor_sync(0xffffffffu, va, 8);
    float pb = __shfl_xor_sync(0xffffffffu, vb, 8);

    c = fmaf(pa, c, va * vb);
    float th = fmaf(2.0f, __fdividef(1.0f, 1.0f + __expf(-2.0f * c)), -1.0f);
    float hv = pb * th;

#pragma unroll
    for (int k = 0; k < HH; k++)
        h[k] = __shfl_sync(0xffffffffu, hv, k, 16);
    return hv;
}

__global__ __launch_bounds__(256, 1)
void lstm3_kernel(
    const float* __restrict__ x,
    const float* __restrict__ Wih1, const float* __restrict__ Whh1,
    const float* __restrict__ bih1, const float* __restrict__ bhh1,
    const float* __restrict__ Wih2, const float* __restrict__ Whh2,
    const float* __restrict__ bih2, const float* __restrict__ bhh2,
    const float* __restrict__ Wih3, const float* __restrict__ Whh3,
    const float* __restrict__ bih3, const float* __restrict__ bhh3,
    float* __restrict__ out)
{
    const int tid  = threadIdx.x;
    const int grp  = tid >> 4;
    const int sub  = tid & 15;
    const int b    = blockIdx.x * 16 + grp;
    const int j    = sub & 7;
    const int half = sub >> 3;

    const int rowA = half * 8 + j;
    const int rowB = 16 + half * 8 + j;

    float wi1A[NIN], wi1B[NIN], uh1A[HH], uh1B[HH];
#pragma unroll
    for (int i = 0; i < NIN; i++) { wi1A[i] = Wih1[rowA * NIN + i]; wi1B[i] = Wih1[rowB * NIN + i]; }
#pragma unroll
    for (int k = 0; k < HH;  k++) { uh1A[k] = Whh1[rowA * HH + k]; uh1B[k] = Whh1[rowB * HH + k]; }
    float b1A = bih1[rowA] + bhh1[rowA];
    float b1B = bih1[rowB] + bhh1[rowB];

    float wi2A[HH], wi2B[HH], uh2A[HH], uh2B[HH];
#pragma unroll
    for (int k = 0; k < HH; k++) {
        wi2A[k] = Wih2[rowA * HH + k]; wi2B[k] = Wih2[rowB * HH + k];
        uh2A[k] = Whh2[rowA * HH + k]; uh2B[k] = Whh2[rowB * HH + k];
    }
    float b2A = bih2[rowA] + bhh2[rowA];
    float b2B = bih2[rowB] + bhh2[rowB];

    float wi3A[HH], wi3B[HH], uh3A[HH], uh3B[HH];
#pragma unroll
    for (int k = 0; k < HH; k++) {
        wi3A[k] = Wih3[rowA * HH + k]; wi3B[k] = Wih3[rowB * HH + k];
        uh3A[k] = Whh3[rowA * HH + k]; uh3B[k] = Whh3[rowB * HH + k];
    }
    float b3A = bih3[rowA] + bhh3[rowA];
    float b3B = bih3[rowB] + bhh3[rowB];

    float h1[HH], h2[HH], h3[HH];
#pragma unroll
    for (int k = 0; k < HH; k++) { h1[k] = 0.f; h2[k] = 0.f; h3[k] = 0.f; }
    float c1 = 0.f, c2 = 0.f, c3 = 0.f;

    const float* xrow = x + (size_t)b * TT * NIN;
    float* outp = out + (size_t)b * D_LSTM;

    float xn[NIN];
#pragma unroll
    for (int i = 0; i < NIN; i++) xn[i] = xrow[i];

    for (int t = 0; t < TT; t++) {
        float xc[NIN];
#pragma unroll
        for (int i = 0; i < NIN; i++) xc[i] = xn[i];
        const int tn = (t + 1 < TT) ? (t + 1) : (TT - 1);
#pragma unroll
        for (int i = 0; i < NIN; i++) xn[i] = xrow[tn * NIN + i];

        (void)cell_step<NIN>(wi1A, wi1B, uh1A, uh1B, b1A, b1B, xc, h1, c1, half);
        (void)cell_step<HH >(wi2A, wi2B, uh2A, uh2B, b2A, b2B, h1, h2, c2, half);
        float hv3 = cell_step<HH>(wi3A, wi3B, uh3A, uh3B, b3A, b3B, h2, h3, c3, half);

        if (half == 0)
            outp[t * HH + j] = hv3;
    }
}

// ---------------------------------------------------------------------------
// tf32 tensor-core GEMM with cp.async double buffering.
// C[M,N] = A[M,K] @ W[N,K]^T + bias, optional relu.
// smem holds raw fp32; cvt.rna.tf32 applied at fragment load (register path),
// matching R2's numerics (rel_err ~2.6e-4) while keeping the async pipeline.
// ---------------------------------------------------------------------------

__device__ __forceinline__ void cp_async16(uint32_t dst, const void* src, int src_bytes) {
    asm volatile("cp.async.cg.shared.global [%0], [%1], 16, %2;\n"
                 :: "r"(dst), "l"(src), "r"(src_bytes));
}
__device__ __forceinline__ void cp_commit() {
    asm volatile("cp.async.commit_group;\n" ::: "memory");
}
template <int N>
__device__ __forceinline__ void cp_wait() {
    asm volatile("cp.async.wait_group %0;\n" :: "n"(N) : "memory");
}

__device__ __forceinline__ uint32_t f2tf32(uint32_t bits) {
    uint32_t r;
    asm("cvt.rna.tf32.f32 %0, %1;" : "=r"(r) : "r"(bits));
    return r;
}

__device__ __forceinline__ void mma_tf32(float (&c)[4], const uint32_t (&a)[4],
                                         const uint32_t (&b)[2]) {
    asm volatile(
        "mma.sync.aligned.m16n8k8.row.col.f32.tf32.tf32.f32 "
        "{%0,%1,%2,%3}, {%4,%5,%6,%7}, {%8,%9}, {%0,%1,%2,%3};"
        : "+f"(c[0]), "+f"(c[1]), "+f"(c[2]), "+f"(c[3])
        : "r"(a[0]), "r"(a[1]), "r"(a[2]), "r"(a[3]), "r"(b[0]), "r"(b[1]));
}

template <int BM, int BN, int BK, bool RELU>
__global__ __launch_bounds__(256)
void gemm_tf32_pipe(const float* __restrict__ A, const float* __restrict__ W,
                    const float* __restrict__ bias, float* __restrict__ C,
                    int M, int N, int K)
{
    constexpr int THREADS = 256;
    constexpr int WARPS_M = 2, WARPS_N = 4;
    constexpr int WM = BM / WARPS_M;       // 64
    constexpr int WN = BN / WARPS_N;       // 32 or 16
    constexpr int MT = WM / 16;            // 4
    constexpr int NT = WN / 8;             // 4 or 2
    constexpr int LD = BK + 4;             // smem row stride (words)

    extern __shared__ uint32_t sm[];
    uint32_t* As = sm;                     // [2][BM*LD]
    uint32_t* Bs = sm + 2 * BM * LD;       // [2][BN*LD]

    const int tid  = threadIdx.x;
    const int lane = tid & 31;
    const int warp = tid >> 5;
    const int wm   = warp / WARPS_N;
    const int wn   = warp % WARPS_N;
    const int g    = lane >> 2;
    const int t    = lane & 3;

    const int m0 = blockIdx.y * BM;
    const int n0 = blockIdx.x * BN;

    const uint32_t as_smem = (uint32_t)__cvta_generic_to_shared(As);
    const uint32_t bs_smem = (uint32_t)__cvta_generic_to_shared(Bs);

    float acc[MT][NT][4];
#pragma unroll
    for (int i = 0; i < MT; i++)
#pragma unroll
        for (int j = 0; j < NT; j++)
#pragma unroll
            for (int q = 0; q < 4; q++) acc[i][j][q] = 0.f;

    constexpr int KQ = BK / 4;                     // float4 per row
    constexpr int A_ITERS = BM * KQ / THREADS;     // 4
    constexpr int B_ITERS = BN * KQ / THREADS;     // 4 or 2

    auto load_tiles = [&](int k0, int stage) {
        const uint32_t a_base = as_smem + (uint32_t)stage * BM * LD * 4;
        const uint32_t b_base = bs_smem + (uint32_t)stage * BN * LD * 4;
#pragma unroll
        for (int r = 0; r < A_ITERS; r++) {
            const int idx = tid + r * THREADS;
            const int row = idx / KQ;
            const int kq  = idx % KQ;
            const int kg  = k0 + kq * 4;
            const bool ok = kg < K;
            const float* src = ok ? &A[(size_t)(m0 + row) * K + kg] : A;
            cp_async16(a_base + (row * LD + kq * 4) * 4, src, ok ? 16 : 0);
        }
#pragma unroll
        for (int r = 0; r < B_ITERS; r++) {
            const int idx = tid + r * THREADS;
            const int row = idx / KQ;
            const int kq  = idx % KQ;
            const int kg  = k0 + kq * 4;
            const bool ok = (n0 + row) < N && kg < K;
            const float* src = ok ? &W[(size_t)(n0 + row) * K + kg] : W;
            cp_async16(b_base + (row * LD + kq * 4) * 4, src, ok ? 16 : 0);
        }
        cp_commit();
    };

    const int nk = (K + BK - 1) / BK;

    load_tiles(0, 0);

    for (int it = 0; it < nk; it++) {
        const int cur = it & 1;
        if (it + 1 < nk) {
            load_tiles((it + 1) * BK, (it + 1) & 1);
            cp_wait<1>();
        } else {
            cp_wait<0>();
        }
        __syncthreads();

        const uint32_t* Ac = As + cur * BM * LD;
        const uint32_t* Bc = Bs + cur * BN * LD;

#pragma unroll
        for (int kk = 0; kk < BK; kk += 8) {
            uint32_t af[MT][4], bf[NT][2];
#pragma unroll
            for (int mt = 0; mt < MT; mt++) {
                const int r = wm * WM + mt * 16 + g;
                af[mt][0] = f2tf32(Ac[(r    ) * LD + kk + t    ]);
                af[mt][1] = f2tf32(Ac[(r + 8) * LD + kk + t    ]);
                af[mt][2] = f2tf32(Ac[(r    ) * LD + kk + t + 4]);
                af[mt][3] = f2tf32(Ac[(r + 8) * LD + kk + t + 4]);
            }
#pragma unroll
            for (int nt = 0; nt < NT; nt++) {
                const int cc = wn * WN + nt * 8 + g;
                bf[nt][0] = f2tf32(Bc[cc * LD + kk + t    ]);
                bf[nt][1] = f2tf32(Bc[cc * LD + kk + t + 4]);
            }
#pragma unroll
            for (int mt = 0; mt < MT; mt++)
#pragma unroll
                for (int nt = 0; nt < NT; nt++)
                    mma_tf32(acc[mt][nt], af[mt], bf[nt]);
        }
        __syncthreads();
    }

    // ---- epilogue: bias (+relu), guarded stores ----
#pragma unroll
    for (int mt = 0; mt < MT; mt++) {
        const int r0 = m0 + wm * WM + mt * 16 + g;
        const int r1 = r0 + 8;
#pragma unroll
        for (int nt = 0; nt < NT; nt++) {
            const int cbase = n0 + wn * WN + nt * 8 + 2 * t;
#pragma unroll
            for (int q = 0; q < 2; q++) {
                const int cn = cbase + q;
                if (cn < N) {
                    const float bv = bias[cn];
                    float v0 = acc[mt][nt][q] + bv;
                    float v1 = acc[mt][nt][2 + q] + bv;
                    if (RELU) { v0 = fmaxf(v0, 0.f); v1 = fmaxf(v1, 0.f); }
                    C[(size_t)r0 * N + cn] = v0;
                    C[(size_t)r1 * N + cn] = v1;
                }
            }
        }
    }
}

// ---------------------------------------------------------------------------
extern "C" void kernel_launch(void* const* d_in, const int* in_sizes, int n_in,
                              void* d_out, int out_size)
{
    const float* x    = (const float*)d_in[0];
    const float* Wih1 = (const float*)d_in[1];
    const float* Whh1 = (const float*)d_in[2];
    const float* bih1 = (const float*)d_in[3];
    const float* bhh1 = (const float*)d_in[4];
    const float* Wih2 = (const float*)d_in[5];
    const float* Whh2 = (const float*)d_in[6];
    const float* bih2 = (const float*)d_in[7];
    const float* bhh2 = (const float*)d_in[8];
    const float* Wih3 = (const float*)d_in[9];
    const float* Whh3 = (const float*)d_in[10];
    const float* bih3 = (const float*)d_in[11];
    const float* bhh3 = (const float*)d_in[12];
    const float* W1   = (const float*)d_in[13];
    const float* b1   = (const float*)d_in[14];
    const float* W2   = (const float*)d_in[15];
    const float* b2   = (const float*)d_in[16];
    const float* W3   = (const float*)d_in[17];
    const float* b3   = (const float*)d_in[18];
    float* out = (float*)d_out;

    float *lstm_o, *a1, *a2;
    cudaGetSymbolAddress((void**)&lstm_o, g_lstm_out);
    cudaGetSymbolAddress((void**)&a1, g_act1);
    cudaGetSymbolAddress((void**)&a2, g_act2);

    constexpr int LD = 36;
    constexpr int SMEM_128 = (2 * 128 * LD + 2 * 128 * LD) * 4;  // 73728
    constexpr int SMEM_64  = (2 * 128 * LD + 2 * 64 * LD) * 4;   // 55296

    static bool attr_done = false;
    if (!attr_done) {
        cudaFuncSetAttribute(gemm_tf32_pipe<128, 128, 32, true>,
                             cudaFuncAttributeMaxDynamicSharedMemorySize, SMEM_128);
        cudaFuncSetAttribute(gemm_tf32_pipe<128, 64, 32, true>,
                             cudaFuncAttributeMaxDynamicSharedMemorySize, SMEM_64);
        cudaFuncSetAttribute(gemm_tf32_pipe<128, 64, 32, false>,
                             cudaFuncAttributeMaxDynamicSharedMemorySize, SMEM_64);
        attr_done = true;
    }

    // 1) fused 3-layer LSTM
    lstm3_kernel<<<BATCH / 16, 256>>>(x,
        Wih1, Whh1, bih1, bhh1,
        Wih2, Whh2, bih2, bhh2,
        Wih3, Whh3, bih3, bhh3,
        lstm_o);

    // 2) MLP head (tf32 tensor cores, cp.async pipelined, RNA at frag load)
    {   // [2048,4872] x [4096,4872]^T -> relu -> [2048,4096]
        dim3 grid(N1 / 128, BATCH / 128);
        gemm_tf32_pipe<128, 128, 32, true><<<grid, 256, SMEM_128>>>(
            lstm_o, W1, b1, a1, BATCH, N1, D_LSTM);
    }
    {   // [2048,4096] x [1024,4096]^T -> relu -> [2048,1024]
        dim3 grid(N2 / 64, BATCH / 128);
        gemm_tf32_pipe<128, 64, 32, true><<<grid, 256, SMEM_64>>>(
            a1, W2, b2, a2, BATCH, N2, N1);
    }
    {   // [2048,1024] x [609,1024]^T -> [2048,609]
        dim3 grid((N3 + 63) / 64, BATCH / 128);
        gemm_tf32_pipe<128, 64, 32, false><<<grid, 256, SMEM_64>>>(
            a2, W3, b3, out, BATCH, N3, N2);
    }
}

// round 5
// speedup vs baseline: 2.7101x; 1.0476x over previous
#include <cuda_runtime.h>
#include <cuda_bf16.h>
#include <cstdint>

// Problem constants
#define BATCH 2048
#define TT    609
#define NIN   5
#define HH    8
#define D_LSTM (TT * HH)     // 4872
#define N1    4096
#define N2    1024
#define N3    609            // == TT

// Scratch (no cudaMalloc allowed) ---------------------------------------------
__device__ float g_lstm_out[BATCH * D_LSTM];   // [2048, 4872]
__device__ float g_act1[BATCH * N1];           // [2048, 4096]
__device__ float g_act2[BATCH * N2];           // [2048, 1024]

// ---------------------------------------------------------------------------
// Fused 3-layer LSTM (unchanged). 16 threads per batch element.
// ---------------------------------------------------------------------------

__device__ __forceinline__ float sigmoidf_fast(float v) {
    float e = __expf(-v);
    return __fdividef(1.0f, 1.0f + e);
}

template <int NI>
__device__ __forceinline__ float cell_step(
    const float (&wA)[NI], const float (&wB)[NI],
    const float (&uA)[HH], const float (&uB)[HH],
    float bA, float bB,
    const float (&in)[NI], float (&h)[HH], float& c, int half)
{
    float gA = bA, gB = bB;
#pragma unroll
    for (int i = 0; i < NI; i++) {
        gA = fmaf(wA[i], in[i], gA);
        gB = fmaf(wB[i], in[i], gB);
    }
#pragma unroll
    for (int k = 0; k < HH; k++) {
        gA = fmaf(uA[k], h[k], gA);
        gB = fmaf(uB[k], h[k], gB);
    }
    float va = sigmoidf_fast(gA);
    float e  = __expf(half ? -gB : (-2.0f * gB));
    float r  = __fdividef(1.0f, 1.0f + e);
    float vb = half ? r : fmaf(2.0f, r, -1.0f);

    float pa = __shfl_xor_sync(0xffffffffu, va, 8);
    float pb = __shfl_xor_sync(0xffffffffu, vb, 8);

    c = fmaf(pa, c, va * vb);
    float th = fmaf(2.0f, __fdividef(1.0f, 1.0f + __expf(-2.0f * c)), -1.0f);
    float hv = pb * th;

#pragma unroll
    for (int k = 0; k < HH; k++)
        h[k] = __shfl_sync(0xffffffffu, hv, k, 16);
    return hv;
}

__global__ __launch_bounds__(256, 1)
void lstm3_kernel(
    const float* __restrict__ x,
    const float* __restrict__ Wih1, const float* __restrict__ Whh1,
    const float* __restrict__ bih1, const float* __restrict__ bhh1,
    const float* __restrict__ Wih2, const float* __restrict__ Whh2,
    const float* __restrict__ bih2, const float* __restrict__ bhh2,
    const float* __restrict__ Wih3, const float* __restrict__ Whh3,
    const float* __restrict__ bih3, const float* __restrict__ bhh3,
    float* __restrict__ out)
{
    const int tid  = threadIdx.x;
    const int grp  = tid >> 4;
    const int sub  = tid & 15;
    const int b    = blockIdx.x * 16 + grp;
    const int j    = sub & 7;
    const int half = sub >> 3;

    const int rowA = half * 8 + j;
    const int rowB = 16 + half * 8 + j;

    float wi1A[NIN], wi1B[NIN], uh1A[HH], uh1B[HH];
#pragma unroll
    for (int i = 0; i < NIN; i++) { wi1A[i] = Wih1[rowA * NIN + i]; wi1B[i] = Wih1[rowB * NIN + i]; }
#pragma unroll
    for (int k = 0; k < HH;  k++) { uh1A[k] = Whh1[rowA * HH + k]; uh1B[k] = Whh1[rowB * HH + k]; }
    float b1A = bih1[rowA] + bhh1[rowA];
    float b1B = bih1[rowB] + bhh1[rowB];

    float wi2A[HH], wi2B[HH], uh2A[HH], uh2B[HH];
#pragma unroll
    for (int k = 0; k < HH; k++) {
        wi2A[k] = Wih2[rowA * HH + k]; wi2B[k] = Wih2[rowB * HH + k];
        uh2A[k] = Whh2[rowA * HH + k]; uh2B[k] = Whh2[rowB * HH + k];
    }
    float b2A = bih2[rowA] + bhh2[rowA];
    float b2B = bih2[rowB] + bhh2[rowB];

    float wi3A[HH], wi3B[HH], uh3A[HH], uh3B[HH];
#pragma unroll
    for (int k = 0; k < HH; k++) {
        wi3A[k] = Wih3[rowA * HH + k]; wi3B[k] = Wih3[rowB * HH + k];
        uh3A[k] = Whh3[rowA * HH + k]; uh3B[k] = Whh3[rowB * HH + k];
    }
    float b3A = bih3[rowA] + bhh3[rowA];
    float b3B = bih3[rowB] + bhh3[rowB];

    float h1[HH], h2[HH], h3[HH];
#pragma unroll
    for (int k = 0; k < HH; k++) { h1[k] = 0.f; h2[k] = 0.f; h3[k] = 0.f; }
    float c1 = 0.f, c2 = 0.f, c3 = 0.f;

    const float* xrow = x + (size_t)b * TT * NIN;
    float* outp = out + (size_t)b * D_LSTM;

    float xn[NIN];
#pragma unroll
    for (int i = 0; i < NIN; i++) xn[i] = xrow[i];

    for (int t = 0; t < TT; t++) {
        float xc[NIN];
#pragma unroll
        for (int i = 0; i < NIN; i++) xc[i] = xn[i];
        const int tn = (t + 1 < TT) ? (t + 1) : (TT - 1);
#pragma unroll
        for (int i = 0; i < NIN; i++) xn[i] = xrow[tn * NIN + i];

        (void)cell_step<NIN>(wi1A, wi1B, uh1A, uh1B, b1A, b1B, xc, h1, c1, half);
        (void)cell_step<HH >(wi2A, wi2B, uh2A, uh2B, b2A, b2B, h1, h2, c2, half);
        float hv3 = cell_step<HH>(wi3A, wi3B, uh3A, uh3B, b3A, b3B, h2, h3, c3, half);

        if (half == 0)
            outp[t * HH + j] = hv3;
    }
}

// ---------------------------------------------------------------------------
// tf32 tensor-core GEMM, cp.async double-buffered, 2x2 warps, big warp tiles,
// fragment double-buffering. cvt.rna.tf32 at fragment load (R2 numerics).
// ---------------------------------------------------------------------------

__device__ __forceinline__ void cp_async16(uint32_t dst, const void* src, int src_bytes) {
    asm volatile("cp.async.cg.shared.global [%0], [%1], 16, %2;\n"
                 :: "r"(dst), "l"(src), "r"(src_bytes));
}
__device__ __forceinline__ void cp_commit() {
    asm volatile("cp.async.commit_group;\n" ::: "memory");
}
template <int N>
__device__ __forceinline__ void cp_wait() {
    asm volatile("cp.async.wait_group %0;\n" :: "n"(N) : "memory");
}

__device__ __forceinline__ uint32_t f2tf32(uint32_t bits) {
    uint32_t r;
    asm("cvt.rna.tf32.f32 %0, %1;" : "=r"(r) : "r"(bits));
    return r;
}

__device__ __forceinline__ void mma_tf32(float (&c)[4], const uint32_t (&a)[4],
                                         const uint32_t (&b)[2]) {
    asm volatile(
        "mma.sync.aligned.m16n8k8.row.col.f32.tf32.tf32.f32 "
        "{%0,%1,%2,%3}, {%4,%5,%6,%7}, {%8,%9}, {%0,%1,%2,%3};"
        : "+f"(c[0]), "+f"(c[1]), "+f"(c[2]), "+f"(c[3])
        : "r"(a[0]), "r"(a[1]), "r"(a[2]), "r"(a[3]), "r"(b[0]), "r"(b[1]));
}

template <int BM, int BN, int BK, bool RELU>
__global__ __launch_bounds__(128, 2)
void gemm_tf32_v2(const float* __restrict__ A, const float* __restrict__ W,
                  const float* __restrict__ bias, float* __restrict__ C,
                  int M, int N, int K)
{
    constexpr int THREADS = 128;
    constexpr int WARPS_M = 2, WARPS_N = 2;
    constexpr int WM = BM / WARPS_M;       // 64
    constexpr int WN = BN / WARPS_N;       // 64 or 32
    constexpr int MT = WM / 16;            // 4
    constexpr int NT = WN / 8;             // 8 or 4
    constexpr int LD = BK + 4;             // smem row stride (words)

    extern __shared__ uint32_t sm[];
    uint32_t* As = sm;                     // [2][BM*LD]
    uint32_t* Bs = sm + 2 * BM * LD;       // [2][BN*LD]

    const int tid  = threadIdx.x;
    const int lane = tid & 31;
    const int warp = tid >> 5;
    const int wm   = warp / WARPS_N;
    const int wn   = warp % WARPS_N;
    const int g    = lane >> 2;
    const int t    = lane & 3;

    const int m0 = blockIdx.y * BM;
    const int n0 = blockIdx.x * BN;

    const uint32_t as_smem = (uint32_t)__cvta_generic_to_shared(As);
    const uint32_t bs_smem = (uint32_t)__cvta_generic_to_shared(Bs);

    float acc[MT][NT][4];
#pragma unroll
    for (int i = 0; i < MT; i++)
#pragma unroll
        for (int j = 0; j < NT; j++)
#pragma unroll
            for (int q = 0; q < 4; q++) acc[i][j][q] = 0.f;

    constexpr int KQ = BK / 4;                     // float4 per row
    constexpr int A_ITERS = BM * KQ / THREADS;     // 8
    constexpr int B_ITERS = BN * KQ / THREADS;     // 8 or 4

    auto load_tiles = [&](int k0, int stage) {
        const uint32_t a_base = as_smem + (uint32_t)stage * BM * LD * 4;
        const uint32_t b_base = bs_smem + (uint32_t)stage * BN * LD * 4;
#pragma unroll
        for (int r = 0; r < A_ITERS; r++) {
            const int idx = tid + r * THREADS;
            const int row = idx / KQ;
            const int kq  = idx % KQ;
            const int kg  = k0 + kq * 4;
            const bool ok = kg < K;
            const float* src = ok ? &A[(size_t)(m0 + row) * K + kg] : A;
            cp_async16(a_base + (row * LD + kq * 4) * 4, src, ok ? 16 : 0);
        }
#pragma unroll
        for (int r = 0; r < B_ITERS; r++) {
            const int idx = tid + r * THREADS;
            const int row = idx / KQ;
            const int kq  = idx % KQ;
            const int kg  = k0 + kq * 4;
            const bool ok = (n0 + row) < N && kg < K;
            const float* src = ok ? &W[(size_t)(n0 + row) * K + kg] : W;
            cp_async16(b_base + (row * LD + kq * 4) * 4, src, ok ? 16 : 0);
        }
        cp_commit();
    };

    const int nk = (K + BK - 1) / BK;

    load_tiles(0, 0);

    uint32_t af[2][MT][4], bf[2][NT][2];

    for (int it = 0; it < nk; it++) {
        const int cur = it & 1;
        if (it + 1 < nk) {
            load_tiles((it + 1) * BK, (it + 1) & 1);
            cp_wait<1>();
        } else {
            cp_wait<0>();
        }
        __syncthreads();

        const uint32_t* Ac = As + cur * BM * LD;
        const uint32_t* Bc = Bs + cur * BN * LD;

        auto ldfrag = [&](int kk, int buf) {
#pragma unroll
            for (int mt = 0; mt < MT; mt++) {
                const int r = wm * WM + mt * 16 + g;
                af[buf][mt][0] = f2tf32(Ac[(r    ) * LD + kk + t    ]);
                af[buf][mt][1] = f2tf32(Ac[(r + 8) * LD + kk + t    ]);
                af[buf][mt][2] = f2tf32(Ac[(r    ) * LD + kk + t + 4]);
                af[buf][mt][3] = f2tf32(Ac[(r + 8) * LD + kk + t + 4]);
            }
#pragma unroll
            for (int nt = 0; nt < NT; nt++) {
                const int cc = wn * WN + nt * 8 + g;
                bf[buf][nt][0] = f2tf32(Bc[cc * LD + kk + t    ]);
                bf[buf][nt][1] = f2tf32(Bc[cc * LD + kk + t + 4]);
            }
        };

        ldfrag(0, 0);
#pragma unroll
        for (int kk = 0; kk < BK; kk += 8) {
            const int cb = (kk >> 3) & 1;
            if (kk + 8 < BK)
                ldfrag(kk + 8, cb ^ 1);
#pragma unroll
            for (int mt = 0; mt < MT; mt++)
#pragma unroll
                for (int nt = 0; nt < NT; nt++)
                    mma_tf32(acc[mt][nt], af[cb][mt], bf[cb][nt]);
        }
        __syncthreads();
    }

    // ---- epilogue: bias (+relu), guarded stores ----
#pragma unroll
    for (int mt = 0; mt < MT; mt++) {
        const int r0 = m0 + wm * WM + mt * 16 + g;
        const int r1 = r0 + 8;
#pragma unroll
        for (int nt = 0; nt < NT; nt++) {
            const int cbase = n0 + wn * WN + nt * 8 + 2 * t;
#pragma unroll
            for (int q = 0; q < 2; q++) {
                const int cn = cbase + q;
                if (cn < N) {
                    const float bv = bias[cn];
                    float v0 = acc[mt][nt][q] + bv;
                    float v1 = acc[mt][nt][2 + q] + bv;
                    if (RELU) { v0 = fmaxf(v0, 0.f); v1 = fmaxf(v1, 0.f); }
                    C[(size_t)r0 * N + cn] = v0;
                    C[(size_t)r1 * N + cn] = v1;
                }
            }
        }
    }
}

// ---------------------------------------------------------------------------
extern "C" void kernel_launch(void* const* d_in, const int* in_sizes, int n_in,
                              void* d_out, int out_size)
{
    const float* x    = (const float*)d_in[0];
    const float* Wih1 = (const float*)d_in[1];
    const float* Whh1 = (const float*)d_in[2];
    const float* bih1 = (const float*)d_in[3];
    const float* bhh1 = (const float*)d_in[4];
    const float* Wih2 = (const float*)d_in[5];
    const float* Whh2 = (const float*)d_in[6];
    const float* bih2 = (const float*)d_in[7];
    const float* bhh2 = (const float*)d_in[8];
    const float* Wih3 = (const float*)d_in[9];
    const float* Whh3 = (const float*)d_in[10];
    const float* bih3 = (const float*)d_in[11];
    const float* bhh3 = (const float*)d_in[12];
    const float* W1   = (const float*)d_in[13];
    const float* b1   = (const float*)d_in[14];
    const float* W2   = (const float*)d_in[15];
    const float* b2   = (const float*)d_in[16];
    const float* W3   = (const float*)d_in[17];
    const float* b3   = (const float*)d_in[18];
    float* out = (float*)d_out;

    float *lstm_o, *a1, *a2;
    cudaGetSymbolAddress((void**)&lstm_o, g_lstm_out);
    cudaGetSymbolAddress((void**)&a1, g_act1);
    cudaGetSymbolAddress((void**)&a2, g_act2);

    constexpr int LD = 36;
    constexpr int SMEM_128 = (2 * 128 * LD + 2 * 128 * LD) * 4;  // 73728
    constexpr int SMEM_64  = (2 * 128 * LD + 2 * 64 * LD) * 4;   // 55296

    static bool attr_done = false;
    if (!attr_done) {
        cudaFuncSetAttribute(gemm_tf32_v2<128, 128, 32, true>,
                             cudaFuncAttributeMaxDynamicSharedMemorySize, SMEM_128);
        cudaFuncSetAttribute(gemm_tf32_v2<128, 64, 32, true>,
                             cudaFuncAttributeMaxDynamicSharedMemorySize, SMEM_64);
        cudaFuncSetAttribute(gemm_tf32_v2<128, 64, 32, false>,
                             cudaFuncAttributeMaxDynamicSharedMemorySize, SMEM_64);
        attr_done = true;
    }

    // 1) fused 3-layer LSTM
    lstm3_kernel<<<BATCH / 16, 256>>>(x,
        Wih1, Whh1, bih1, bhh1,
        Wih2, Whh2, bih2, bhh2,
        Wih3, Whh3, bih3, bhh3,
        lstm_o);

    // 2) MLP head (tf32, 2x2 warps, 64x64 warp tile on GEMM1)
    {   // [2048,4872] x [4096,4872]^T -> relu -> [2048,4096]
        dim3 grid(N1 / 128, BATCH / 128);
        gemm_tf32_v2<128, 128, 32, true><<<grid, 128, SMEM_128>>>(
            lstm_o, W1, b1, a1, BATCH, N1, D_LSTM);
    }
    {   // [2048,4096] x [1024,4096]^T -> relu -> [2048,1024]
        dim3 grid(N2 / 64, BATCH / 128);
        gemm_tf32_v2<128, 64, 32, true><<<grid, 128, SMEM_64>>>(
            a1, W2, b2, a2, BATCH, N2, N1);
    }
    {   // [2048,1024] x [609,1024]^T -> [2048,609]
        dim3 grid((N3 + 63) / 64, BATCH / 128);
        gemm_tf32_v2<128, 64, 32, false><<<grid, 128, SMEM_64>>>(
            a2, W3, b3, out, BATCH, N3, N2);
    }
}